// round 1
// baseline (speedup 1.0000x reference)
#include <cuda_runtime.h>
#include <math.h>

#define NT   512        // threads per block
#define GBSZ 16         // batch rows per block
#define HID  128
#define LIFTN 32

// ---------------- shared memory layout (float offsets) ----------------
#define OFF_WHH  0                      // 384*128 = 49152 (swizzled float4)
#define OFF_H    49152                  // 16*128  = 2048
#define OFF_LIFT 51200                  // 16*32   = 512
#define OFF_WHD  51712                  // 19*132  = 2508 -> 2512
#define OFF_WLF  54224                  // 9*32    = 288
#define OFF_BIH  54512                  // 384
#define OFF_BHH  54896                  // 384
#define OFF_BHD  55280                  // 19 -> 20
#define OFF_BLF  55300                  // 32
#define OFF_U2Y  55332                  // 20
#define OFF_FEAT 55352                  // 16*12 = 192
#define OFF_TH   55544                  // 16*20 = 320
#define OFF_Y    55864                  // 16*16 = 256
#define OFF_YT   56120                  // 16*16 = 256
#define OFF_DT   56376                  // 16
#define SMEM_FLOATS 56392
#define SMEM_BYTES (SMEM_FLOATS * 4)    // 225568 <= 232448

// transposed w_ih planes: [gate][i(0..31)][j(0..127)]
__device__ float g_wihT[3 * 32 * 128];

__global__ void prep_wih_kernel(const float* __restrict__ w_ih) {
    int idx = blockIdx.x * blockDim.x + threadIdx.x;
    if (idx < 3 * 32 * 128) {
        int gate = idx / (32 * 128);
        int r    = idx % (32 * 128);
        int i    = r / 128;
        int j    = r % 128;
        g_wihT[idx] = w_ih[(gate * 128 + j) * 32 + i];
    }
}

__device__ __forceinline__ float sigmoid_acc(float x) {
    return 1.0f / (1.0f + __expf(-x));
}
__device__ __forceinline__ float tanh_acc(float x) {
    float ax = fabsf(x);
    float e  = __expf(2.0f * ax);          // inf-safe
    float t  = 1.0f - 2.0f / (e + 1.0f);
    return copysignf(t, x);
}

__global__ __launch_bounds__(NT, 1)
void rnn_chain_kernel(
    const float* __restrict__ y0,       // (B,5)
    const float* __restrict__ u_seq,    // (B,K,4)
    const float* __restrict__ dt_seq,   // (B,K)
    const float* __restrict__ y_seq,    // (B,K,5)
    const float* __restrict__ W_lift,   // (9,32)
    const float* __restrict__ b_lift,   // (32)
    const float* __restrict__ w_hh,     // (384,128)
    const float* __restrict__ b_ih,     // (384)
    const float* __restrict__ b_hh,     // (384)
    const float* __restrict__ W_head,   // (128,19)
    const float* __restrict__ b_head,   // (19)
    const float* __restrict__ u2y,      // (4,5)
    const int*   __restrict__ tfe,      // scalar
    float* __restrict__ out_y,          // (B,K,5)
    float* __restrict__ out_theta,      // (B,K,19)
    int B, int K)
{
    extern __shared__ float sm[];
    const int tid  = threadIdx.x;
    const int lane = tid & 31;
    const int wid  = tid >> 5;            // 0..15  (= batch row within block for warp phases)
    const int bg   = blockIdx.x * GBSZ;
    const int tf_every = tfe[0];

    // ---------- one-time loads into shared ----------
    {
        // w_hh: swizzled float4 store for conflict-free LDS.128
        const float4* src = (const float4*)w_hh;
        float4* w4 = (float4*)(sm + OFF_WHH);
        for (int idx = tid; idx < 384 * 32; idx += NT) {
            int j = idx >> 5, q = idx & 31;
            w4[(j << 5) | (q ^ (j & 7))] = src[idx];
        }
        // W_head transposed: [o][i] pitch 132
        for (int idx = tid; idx < 19 * 128; idx += NT) {
            int o = idx / 128, i = idx % 128;
            sm[OFF_WHD + o * 132 + i] = W_head[i * 19 + o];
        }
        for (int idx = tid; idx < 288; idx += NT) sm[OFF_WLF + idx] = W_lift[idx];
        for (int idx = tid; idx < 384; idx += NT) {
            sm[OFF_BIH + idx] = b_ih[idx];
            sm[OFF_BHH + idx] = b_hh[idx];
        }
        if (tid < 19) sm[OFF_BHD + tid] = b_head[tid];
        if (tid < 32) sm[OFF_BLF + tid] = b_lift[tid];
        if (tid < 20) sm[OFF_U2Y + tid] = u2y[tid];
        // h = 0
        for (int idx = tid; idx < GBSZ * HID; idx += NT) sm[OFF_H + idx] = 0.0f;
        // y_full init: 0.01 everywhere, obs states 3p get + y0
        for (int idx = tid; idx < GBSZ * 16; idx += NT) {
            int g = idx >> 4, i = idx & 15;
            float v = 0.0f;
            if (i < 13) {
                v = 0.01f;
                if (i % 3 == 0) {
                    int p = i / 3;
                    int bgg = bg + g;
                    if (bgg < B) v = 0.01f + y0[bgg * 5 + p];
                }
            }
            sm[OFF_Y  + idx] = v;
            sm[OFF_YT + idx] = 0.0f;   // pads stay 0 forever
        }
    }
    __syncthreads();

    const int j  = tid & 127;
    const int gq = tid >> 7;              // 0..3
    const int g0 = gq * 4;
    const int sjw = j & 7;

    const int   gA  = wid;                // warp-phase batch row
    const int   bgg = bg + gA;
    const bool  vb  = (bgg < B);

    for (int k = 0; k < K; ++k) {
        // ================= A: features + lift (warp-local on row gA) ==========
        {
            bool tf = (k > 0) && (k % tf_every == 0);
            if (lane < 4) {
                float u = vb ? u_seq[((size_t)bgg * K + k) * 4 + lane] : 0.0f;
                sm[OFF_FEAT + gA * 12 + lane] = u;
            } else if (lane < 9) {
                int p = lane - 4;
                float yp;
                if (tf) yp = vb ? y_seq[((size_t)bgg * K + (k - 1)) * 5 + p] : 0.0f;
                else    yp = sm[OFF_Y + gA * 16 + 3 * p];
                sm[OFF_FEAT + gA * 12 + 4 + p] = yp;
            } else if (lane == 9) {
                sm[OFF_DT + gA] = vb ? dt_seq[(size_t)bgg * K + k] : 0.01f;
            }
            __syncwarp();
            // lifted: lane = output channel c (32 per row)
            float acc = sm[OFF_BLF + lane];
            #pragma unroll
            for (int i = 0; i < 9; ++i)
                acc = fmaf(sm[OFF_FEAT + gA * 12 + i], sm[OFF_WLF + i * 32 + lane], acc);
            float s = sigmoid_acc(acc);
            sm[OFF_LIFT + gA * 32 + lane] = acc * s;   // silu
        }
        __syncthreads();

        // ================= B: gx (w_ih^T from L2) + gh (w_hh from smem) =======
        float aR[4], aZ[4], aNx[4], aNh[4];
        {
            float biR = sm[OFF_BIH + j],       bhR = sm[OFF_BHH + j];
            float biZ = sm[OFF_BIH + 128 + j], bhZ = sm[OFF_BHH + 128 + j];
            float biN = sm[OFF_BIH + 256 + j], bhN = sm[OFF_BHH + 256 + j];
            #pragma unroll
            for (int t = 0; t < 4; ++t) {
                aR[t] = biR + bhR; aZ[t] = biZ + bhZ; aNx[t] = biN; aNh[t] = bhN;
            }
        }
        // gx
        #pragma unroll 4
        for (int i = 0; i < 32; ++i) {
            float wr = g_wihT[(0 * 32 + i) * 128 + j];
            float wz = g_wihT[(1 * 32 + i) * 128 + j];
            float wn = g_wihT[(2 * 32 + i) * 128 + j];
            #pragma unroll
            for (int t = 0; t < 4; ++t) {
                float lf = sm[OFF_LIFT + (g0 + t) * 32 + i];
                aR[t]  = fmaf(lf, wr, aR[t]);
                aZ[t]  = fmaf(lf, wz, aZ[t]);
                aNx[t] = fmaf(lf, wn, aNx[t]);
            }
        }
        // gh
        {
            const float4* w4 = (const float4*)(sm + OFF_WHH);
            const float4* h4 = (const float4*)(sm + OFF_H);
            #pragma unroll 4
            for (int q = 0; q < 32; ++q) {
                int qs = q ^ sjw;
                float4 wr = w4[((j      ) << 5) | qs];
                float4 wz = w4[((j + 128) << 5) | qs];
                float4 wn = w4[((j + 256) << 5) | qs];
                #pragma unroll
                for (int t = 0; t < 4; ++t) {
                    float4 hv = h4[(g0 + t) * 32 + q];
                    aR[t]  = fmaf(hv.x, wr.x, aR[t]);
                    aR[t]  = fmaf(hv.y, wr.y, aR[t]);
                    aR[t]  = fmaf(hv.z, wr.z, aR[t]);
                    aR[t]  = fmaf(hv.w, wr.w, aR[t]);
                    aZ[t]  = fmaf(hv.x, wz.x, aZ[t]);
                    aZ[t]  = fmaf(hv.y, wz.y, aZ[t]);
                    aZ[t]  = fmaf(hv.z, wz.z, aZ[t]);
                    aZ[t]  = fmaf(hv.w, wz.w, aZ[t]);
                    aNh[t] = fmaf(hv.x, wn.x, aNh[t]);
                    aNh[t] = fmaf(hv.y, wn.y, aNh[t]);
                    aNh[t] = fmaf(hv.z, wn.z, aNh[t]);
                    aNh[t] = fmaf(hv.w, wn.w, aNh[t]);
                }
            }
        }
        // ================= C: gates + h update ================================
        float hnew[4];
        #pragma unroll
        for (int t = 0; t < 4; ++t) {
            float r  = sigmoid_acc(aR[t]);
            float z  = sigmoid_acc(aZ[t]);
            float n  = tanh_acc(fmaf(r, aNh[t], aNx[t]));
            float ho = sm[OFF_H + (g0 + t) * HID + j];
            hnew[t]  = fmaf(z, ho - n, n);          // (1-z)n + z h
        }
        __syncthreads();   // all reads of h done (B-phase + C-phase)
        #pragma unroll
        for (int t = 0; t < 4; ++t)
            sm[OFF_H + (g0 + t) * HID + j] = hnew[t];
        __syncthreads();   // h_new visible to all

        // ================= D: head (warp-local on row gA) =====================
        {
            int o = (lane < 19) ? lane : 18;
            const float4* hh = (const float4*)(sm + OFF_H + gA * HID);
            const float4* wt = (const float4*)(sm + OFF_WHD + o * 132);
            float p0 = 0.0f, p1 = 0.0f;
            #pragma unroll 8
            for (int i4 = 0; i4 < 32; i4 += 2) {
                float4 h0 = hh[i4],   w0 = wt[i4];
                float4 h1 = hh[i4+1], w1 = wt[i4+1];
                p0 = fmaf(h0.x, w0.x, p0); p0 = fmaf(h0.y, w0.y, p0);
                p0 = fmaf(h0.z, w0.z, p0); p0 = fmaf(h0.w, w0.w, p0);
                p1 = fmaf(h1.x, w1.x, p1); p1 = fmaf(h1.y, w1.y, p1);
                p1 = fmaf(h1.z, w1.z, p1); p1 = fmaf(h1.w, w1.w, p1);
            }
            float acc = sm[OFF_BHD + o] + p0 + p1;
            float th  = fmaf(1.999f, sigmoid_acc(acc), 0.001f);  // gamma
            if (lane < 19) {
                sm[OFF_TH + gA * 20 + lane] = th;
                if (vb) out_theta[((size_t)bgg * K + k) * 19 + lane] = th;
            }
        }
        __syncwarp();

        // ================= E: obs jump + RK4 (warp-local on row gA) ===========
        {
            float dt = sm[OFF_DT + gA];
            if (lane < 5) {
                float jp = 0.0f;
                #pragma unroll
                for (int u = 0; u < 4; ++u)
                    jp = fmaf(sm[OFF_FEAT + gA * 12 + u], sm[OFF_U2Y + u * 5 + lane], jp);
                sm[OFF_Y + gA * 16 + 3 * lane] += jp;
            }
            __syncwarp();

            const float* th = sm + OFF_TH + gA * 20;
            int   i  = lane;
            bool  act = (i < 13);
            int   ii = act ? i : 13;
            int   im = (ii > 0) ? ii - 1 : 0;
            int   ip = ii + 1;                // <= 14, pads are 0
            float ca = 0.0f, cb = 0.0f, cc = 0.0f;
            if (i == 0)       { cb = -th[0];  cc = th[12]; }
            else if (i == 12) { ca = th[11];  cb = -th[18]; }
            else if (i < 12) {
                if (i & 1) { ca = th[i-1]; cb = -(th[12 + (i >> 1)] + th[i]);
                             cc = (i == 11) ? th[18] : 0.0f; }
                else       { ca = th[i-1]; cb = -th[i]; cc = th[12 + (i >> 1)]; }
            }

            float* yv = sm + OFF_Y  + gA * 16;
            float* yt = sm + OFF_YT + gA * 16;
            float y0v = yv[ii];
            float hdt = 0.5f * dt;

            // stage 1 (from yv)
            float ym = yv[im], yc = yv[ii], yp = yv[ip];
            float d1 = ca * ym + cb * yc + cc * yp;
            float ks = d1;
            __syncwarp();
            if (act) yt[i] = fmaf(hdt, d1, y0v);
            __syncwarp();
            // stage 2
            ym = yt[im]; yc = yt[ii]; yp = yt[ip];
            float d2 = ca * ym + cb * yc + cc * yp;
            ks = fmaf(2.0f, d2, ks);
            __syncwarp();
            if (act) yt[i] = fmaf(hdt, d2, y0v);
            __syncwarp();
            // stage 3
            ym = yt[im]; yc = yt[ii]; yp = yt[ip];
            float d3 = ca * ym + cb * yc + cc * yp;
            ks = fmaf(2.0f, d3, ks);
            __syncwarp();
            if (act) yt[i] = fmaf(dt, d3, y0v);
            __syncwarp();
            // stage 4
            ym = yt[im]; yc = yt[ii]; yp = yt[ip];
            float d4 = ca * ym + cb * yc + cc * yp;
            ks += d4;

            float ynew = fmaf(dt * (1.0f / 6.0f), ks, y0v);
            ynew = fmaxf(ynew, 0.0f);
            __syncwarp();
            if (act) yv[i] = ynew;
            __syncwarp();
            if (lane < 5 && vb)
                out_y[((size_t)bgg * K + k) * 5 + lane] = yv[3 * lane];
        }
        // no extra block sync needed: next-iter cross-warp reads (lifted_s, h_s)
        // are ordered by the syncthreads at top of B / after C.
    }
}

extern "C" void kernel_launch(void* const* d_in, const int* in_sizes, int n_in,
                              void* d_out, int out_size) {
    const float* y0     = (const float*)d_in[0];
    const float* u_seq  = (const float*)d_in[1];
    const float* dt_seq = (const float*)d_in[2];
    const float* y_seq  = (const float*)d_in[3];
    const float* W_lift = (const float*)d_in[4];
    const float* b_lift = (const float*)d_in[5];
    const float* w_ih   = (const float*)d_in[6];
    const float* w_hh   = (const float*)d_in[7];
    const float* b_ih   = (const float*)d_in[8];
    const float* b_hh   = (const float*)d_in[9];
    const float* W_head = (const float*)d_in[10];
    const float* b_head = (const float*)d_in[11];
    const float* u2y    = (const float*)d_in[12];
    const int*   tfe    = (const int*)d_in[13];

    int B = in_sizes[0] / 5;
    int K = in_sizes[1] / (B * 4);

    float* out_y     = (float*)d_out;
    float* out_theta = (float*)d_out + (size_t)B * K * 5;

    prep_wih_kernel<<<(3 * 32 * 128 + 255) / 256, 256>>>(w_ih);

    cudaFuncSetAttribute(rnn_chain_kernel,
                         cudaFuncAttributeMaxDynamicSharedMemorySize, SMEM_BYTES);

    int grid = (B + GBSZ - 1) / GBSZ;
    rnn_chain_kernel<<<grid, NT, SMEM_BYTES>>>(
        y0, u_seq, dt_seq, y_seq, W_lift, b_lift, w_hh, b_ih, b_hh,
        W_head, b_head, u2y, tfe, out_y, out_theta, B, K);
}

// round 2
// speedup vs baseline: 1.1407x; 1.1407x over previous
#include <cuda_runtime.h>
#include <math.h>

#define NT   512        // threads per block
#define GBSZ 16         // batch rows per block
#define HID  128
#define LIFTN 32

// ---------------- shared memory layout (float offsets) ----------------
#define OFF_WHH  0                      // 384*128 = 49152 (swizzled float4)
#define OFF_H    49152                  // 16*128  = 2048
#define OFF_LIFT 51200                  // 16*32   = 512
#define OFF_WHD  51712                  // 19*132  = 2508 -> 2512
#define OFF_WLF  54224                  // 9*32    = 288
#define OFF_BIH  54512                  // 384
#define OFF_BHH  54896                  // 384
#define OFF_BHD  55280                  // 19 -> 20
#define OFF_BLF  55300                  // 32
#define OFF_U2Y  55332                  // 20
#define OFF_FEAT 55352                  // 16*12 = 192
#define OFF_TH   55544                  // 16*20 = 320
#define OFF_Y    55864                  // 16*16 = 256
#define OFF_YT   56120                  // 16*16 = 256
#define OFF_DT   56376                  // 16
#define SMEM_FLOATS 56392
#define SMEM_BYTES (SMEM_FLOATS * 4)    // 225568 <= 232448

typedef unsigned long long ull;

// packed w_ih: [gate][i_pair(0..15)][j(0..127)] of float2 (i=2p, 2p+1)
__device__ float g_wihP[3 * 16 * 128 * 2];

__global__ void prep_wih_kernel(const float* __restrict__ w_ih) {
    int idx = blockIdx.x * blockDim.x + threadIdx.x;   // over 3*16*128
    if (idx < 3 * 16 * 128) {
        int gate = idx / (16 * 128);
        int r    = idx % (16 * 128);
        int p    = r / 128;
        int j    = r % 128;
        g_wihP[idx * 2 + 0] = w_ih[(gate * 128 + j) * 32 + 2 * p + 0];
        g_wihP[idx * 2 + 1] = w_ih[(gate * 128 + j) * 32 + 2 * p + 1];
    }
}

__device__ __forceinline__ float sigmoid_acc(float x) {
    return 1.0f / (1.0f + __expf(-x));
}
__device__ __forceinline__ float tanh_acc(float x) {
    float ax = fabsf(x);
    float e  = __expf(2.0f * ax);          // inf-safe
    float t  = 1.0f - 2.0f / (e + 1.0f);
    return copysignf(t, x);
}

// packed 2x fp32 fma: lo,hi computed independently (bitwise == two fmaf)
__device__ __forceinline__ ull ffma2(ull a, ull b, ull c) {
    ull d;
    asm("fma.rn.f32x2 %0, %1, %2, %3;" : "=l"(d) : "l"(a), "l"(b), "l"(c));
    return d;
}
__device__ __forceinline__ float red2(ull v) {
    float lo, hi;
    asm("mov.b64 {%0,%1}, %2;" : "=f"(lo), "=f"(hi) : "l"(v));
    return lo + hi;
}

__global__ __launch_bounds__(NT, 1)
void rnn_chain_kernel(
    const float* __restrict__ y0,       // (B,5)
    const float* __restrict__ u_seq,    // (B,K,4)
    const float* __restrict__ dt_seq,   // (B,K)
    const float* __restrict__ y_seq,    // (B,K,5)
    const float* __restrict__ W_lift,   // (9,32)
    const float* __restrict__ b_lift,   // (32)
    const float* __restrict__ w_hh,     // (384,128)
    const float* __restrict__ b_ih,     // (384)
    const float* __restrict__ b_hh,     // (384)
    const float* __restrict__ W_head,   // (128,19)
    const float* __restrict__ b_head,   // (19)
    const float* __restrict__ u2y,      // (4,5)
    const int*   __restrict__ tfe,      // scalar
    float* __restrict__ out_y,          // (B,K,5)
    float* __restrict__ out_theta,      // (B,K,19)
    int B, int K)
{
    extern __shared__ float sm[];
    const int tid  = threadIdx.x;
    const int lane = tid & 31;
    const int wid  = tid >> 5;            // 0..15
    const int bg   = blockIdx.x * GBSZ;
    const int tf_every = tfe[0];

    // ---------- one-time loads into shared ----------
    {
        // w_hh: swizzled float4 store for conflict-free LDS.128
        const float4* src = (const float4*)w_hh;
        float4* w4 = (float4*)(sm + OFF_WHH);
        for (int idx = tid; idx < 384 * 32; idx += NT) {
            int j = idx >> 5, q = idx & 31;
            w4[(j << 5) | (q ^ (j & 7))] = src[idx];
        }
        // W_head transposed: [o][i] pitch 132
        for (int idx = tid; idx < 19 * 128; idx += NT) {
            int o = idx / 128, i = idx % 128;
            sm[OFF_WHD + o * 132 + i] = W_head[i * 19 + o];
        }
        for (int idx = tid; idx < 288; idx += NT) sm[OFF_WLF + idx] = W_lift[idx];
        for (int idx = tid; idx < 384; idx += NT) {
            sm[OFF_BIH + idx] = b_ih[idx];
            sm[OFF_BHH + idx] = b_hh[idx];
        }
        if (tid < 19) sm[OFF_BHD + tid] = b_head[tid];
        if (tid < 32) sm[OFF_BLF + tid] = b_lift[tid];
        if (tid < 20) sm[OFF_U2Y + tid] = u2y[tid];
        for (int idx = tid; idx < GBSZ * HID; idx += NT) sm[OFF_H + idx] = 0.0f;
        for (int idx = tid; idx < GBSZ * 16; idx += NT) {
            int g = idx >> 4, i = idx & 15;
            float v = 0.0f;
            if (i < 13) {
                v = 0.01f;
                if (i % 3 == 0) {
                    int p = i / 3;
                    int bgg = bg + g;
                    if (bgg < B) v = 0.01f + y0[bgg * 5 + p];
                }
            }
            sm[OFF_Y  + idx] = v;
            sm[OFF_YT + idx] = 0.0f;
        }
    }
    __syncthreads();

    const int j  = tid & 127;
    const int gq = tid >> 7;              // 0..3
    const int g0 = gq * 4;
    const int sjw = j & 7;

    const int   gA  = wid;                // warp-phase batch row
    const int   bgg = bg + gA;
    const bool  vb  = (bgg < B);

    for (int k = 0; k < K; ++k) {
        // ================= A: features + lift (warp-local on row gA) ==========
        {
            bool tf = (k > 0) && (k % tf_every == 0);
            if (lane < 4) {
                float u = vb ? u_seq[((size_t)bgg * K + k) * 4 + lane] : 0.0f;
                sm[OFF_FEAT + gA * 12 + lane] = u;
            } else if (lane < 9) {
                int p = lane - 4;
                float yp;
                if (tf) yp = vb ? y_seq[((size_t)bgg * K + (k - 1)) * 5 + p] : 0.0f;
                else    yp = sm[OFF_Y + gA * 16 + 3 * p];
                sm[OFF_FEAT + gA * 12 + 4 + p] = yp;
            } else if (lane == 9) {
                sm[OFF_DT + gA] = vb ? dt_seq[(size_t)bgg * K + k] : 0.01f;
            }
            __syncwarp();
            float acc = sm[OFF_BLF + lane];
            #pragma unroll
            for (int i = 0; i < 9; ++i)
                acc = fmaf(sm[OFF_FEAT + gA * 12 + i], sm[OFF_WLF + i * 32 + lane], acc);
            float s = sigmoid_acc(acc);
            sm[OFF_LIFT + gA * 32 + lane] = acc * s;   // silu
        }
        __syncthreads();

        // ================= B: gx + gh with packed f32x2 (even/odd i split) ====
        ull aR2[4], aZ2[4], aNx2[4], aNh2[4];
        #pragma unroll
        for (int t = 0; t < 4; ++t) { aR2[t] = 0ULL; aZ2[t] = 0ULL; aNx2[t] = 0ULL; aNh2[t] = 0ULL; }

        // gx: w_ih packed [gate][p][j] float2, lifted as u64 pairs (broadcast)
        {
            const ull* wP  = (const ull*)g_wihP;
            const ull* lf2 = (const ull*)(sm + OFF_LIFT);
            #pragma unroll 4
            for (int p = 0; p < 16; ++p) {
                ull wr = wP[(0 * 16 + p) * 128 + j];
                ull wz = wP[(1 * 16 + p) * 128 + j];
                ull wn = wP[(2 * 16 + p) * 128 + j];
                #pragma unroll
                for (int t = 0; t < 4; ++t) {
                    ull lf = lf2[(g0 + t) * 16 + p];
                    aR2[t]  = ffma2(lf, wr, aR2[t]);
                    aZ2[t]  = ffma2(lf, wz, aZ2[t]);
                    aNx2[t] = ffma2(lf, wn, aNx2[t]);
                }
            }
        }
        // gh: w_hh float4 = 2 packed i-pairs, h float4 = 2 packed i-pairs
        {
            const ulonglong2* w2 = (const ulonglong2*)(sm + OFF_WHH);
            const ulonglong2* h2 = (const ulonglong2*)(sm + OFF_H);
            #pragma unroll 2
            for (int q = 0; q < 32; ++q) {
                int qs = q ^ sjw;
                ulonglong2 wr = w2[((j      ) << 5) | qs];
                ulonglong2 wz = w2[((j + 128) << 5) | qs];
                ulonglong2 wn = w2[((j + 256) << 5) | qs];
                #pragma unroll
                for (int t = 0; t < 4; ++t) {
                    ulonglong2 hv = h2[(g0 + t) * 32 + q];
                    aR2[t]  = ffma2(hv.x, wr.x, aR2[t]);
                    aR2[t]  = ffma2(hv.y, wr.y, aR2[t]);
                    aZ2[t]  = ffma2(hv.x, wz.x, aZ2[t]);
                    aZ2[t]  = ffma2(hv.y, wz.y, aZ2[t]);
                    aNh2[t] = ffma2(hv.x, wn.x, aNh2[t]);
                    aNh2[t] = ffma2(hv.y, wn.y, aNh2[t]);
                }
            }
        }
        // ================= C: gates + h update ================================
        float hnew[4];
        {
            float biR = sm[OFF_BIH + j],       bhR = sm[OFF_BHH + j];
            float biZ = sm[OFF_BIH + 128 + j], bhZ = sm[OFF_BHH + 128 + j];
            float biN = sm[OFF_BIH + 256 + j], bhN = sm[OFF_BHH + 256 + j];
            #pragma unroll
            for (int t = 0; t < 4; ++t) {
                float r  = sigmoid_acc(red2(aR2[t]) + biR + bhR);
                float z  = sigmoid_acc(red2(aZ2[t]) + biZ + bhZ);
                float nx = red2(aNx2[t]) + biN;
                float nh = red2(aNh2[t]) + bhN;
                float n  = tanh_acc(fmaf(r, nh, nx));
                float ho = sm[OFF_H + (g0 + t) * HID + j];
                hnew[t]  = fmaf(z, ho - n, n);          // (1-z)n + z h
            }
        }
        __syncthreads();   // all reads of h done
        #pragma unroll
        for (int t = 0; t < 4; ++t)
            sm[OFF_H + (g0 + t) * HID + j] = hnew[t];
        __syncthreads();   // h_new visible to all

        // ================= D: head (warp-local on row gA, packed) =============
        {
            int o = (lane < 19) ? lane : 18;
            const ull* hh = (const ull*)(sm + OFF_H + gA * HID);     // 64 u64
            const ull* wt = (const ull*)(sm + OFF_WHD + o * 132);
            ull p0 = 0ULL, p1 = 0ULL;
            #pragma unroll 8
            for (int i = 0; i < 64; i += 2) {
                p0 = ffma2(hh[i],     wt[i],     p0);
                p1 = ffma2(hh[i + 1], wt[i + 1], p1);
            }
            float acc = sm[OFF_BHD + o] + red2(p0) + red2(p1);
            float th  = fmaf(1.999f, sigmoid_acc(acc), 0.001f);  // gamma
            if (lane < 19) {
                sm[OFF_TH + gA * 20 + lane] = th;
                if (vb) out_theta[((size_t)bgg * K + k) * 19 + lane] = th;
            }
        }
        __syncwarp();

        // ================= E: obs jump + RK4 (warp-local on row gA) ===========
        {
            float dt = sm[OFF_DT + gA];
            if (lane < 5) {
                float jp = 0.0f;
                #pragma unroll
                for (int u = 0; u < 4; ++u)
                    jp = fmaf(sm[OFF_FEAT + gA * 12 + u], sm[OFF_U2Y + u * 5 + lane], jp);
                sm[OFF_Y + gA * 16 + 3 * lane] += jp;
            }
            __syncwarp();

            const float* th = sm + OFF_TH + gA * 20;
            int   i  = lane;
            bool  act = (i < 13);
            int   ii = act ? i : 13;
            int   im = (ii > 0) ? ii - 1 : 0;
            int   ip = ii + 1;                // <= 14, pads are 0
            float ca = 0.0f, cb = 0.0f, cc = 0.0f;
            if (i == 0)       { cb = -th[0];  cc = th[12]; }
            else if (i == 12) { ca = th[11];  cb = -th[18]; }
            else if (i < 12) {
                if (i & 1) { ca = th[i-1]; cb = -(th[12 + (i >> 1)] + th[i]);
                             cc = (i == 11) ? th[18] : 0.0f; }
                else       { ca = th[i-1]; cb = -th[i]; cc = th[12 + (i >> 1)]; }
            }

            float* yv = sm + OFF_Y  + gA * 16;
            float* yt = sm + OFF_YT + gA * 16;
            float y0v = yv[ii];
            float hdt = 0.5f * dt;

            float ym = yv[im], yc = yv[ii], yp = yv[ip];
            float d1 = ca * ym + cb * yc + cc * yp;
            float ks = d1;
            __syncwarp();
            if (act) yt[i] = fmaf(hdt, d1, y0v);
            __syncwarp();
            ym = yt[im]; yc = yt[ii]; yp = yt[ip];
            float d2 = ca * ym + cb * yc + cc * yp;
            ks = fmaf(2.0f, d2, ks);
            __syncwarp();
            if (act) yt[i] = fmaf(hdt, d2, y0v);
            __syncwarp();
            ym = yt[im]; yc = yt[ii]; yp = yt[ip];
            float d3 = ca * ym + cb * yc + cc * yp;
            ks = fmaf(2.0f, d3, ks);
            __syncwarp();
            if (act) yt[i] = fmaf(dt, d3, y0v);
            __syncwarp();
            ym = yt[im]; yc = yt[ii]; yp = yt[ip];
            float d4 = ca * ym + cb * yc + cc * yp;
            ks += d4;

            float ynew = fmaf(dt * (1.0f / 6.0f), ks, y0v);
            ynew = fmaxf(ynew, 0.0f);
            __syncwarp();
            if (act) yv[i] = ynew;
            __syncwarp();
            if (lane < 5 && vb)
                out_y[((size_t)bgg * K + k) * 5 + lane] = yv[3 * lane];
        }
    }
}

extern "C" void kernel_launch(void* const* d_in, const int* in_sizes, int n_in,
                              void* d_out, int out_size) {
    const float* y0     = (const float*)d_in[0];
    const float* u_seq  = (const float*)d_in[1];
    const float* dt_seq = (const float*)d_in[2];
    const float* y_seq  = (const float*)d_in[3];
    const float* W_lift = (const float*)d_in[4];
    const float* b_lift = (const float*)d_in[5];
    const float* w_ih   = (const float*)d_in[6];
    const float* w_hh   = (const float*)d_in[7];
    const float* b_ih   = (const float*)d_in[8];
    const float* b_hh   = (const float*)d_in[9];
    const float* W_head = (const float*)d_in[10];
    const float* b_head = (const float*)d_in[11];
    const float* u2y    = (const float*)d_in[12];
    const int*   tfe    = (const int*)d_in[13];

    int B = in_sizes[0] / 5;
    int K = in_sizes[1] / (B * 4);

    float* out_y     = (float*)d_out;
    float* out_theta = (float*)d_out + (size_t)B * K * 5;

    prep_wih_kernel<<<(3 * 16 * 128 + 255) / 256, 256>>>(w_ih);

    cudaFuncSetAttribute(rnn_chain_kernel,
                         cudaFuncAttributeMaxDynamicSharedMemorySize, SMEM_BYTES);

    int grid = (B + GBSZ - 1) / GBSZ;
    rnn_chain_kernel<<<grid, NT, SMEM_BYTES>>>(
        y0, u_seq, dt_seq, y_seq, W_lift, b_lift, w_hh, b_ih, b_hh,
        W_head, b_head, u2y, tfe, out_y, out_theta, B, K);
}